// round 1
// baseline (speedup 1.0000x reference)
#include <cuda_runtime.h>
#include <cuda_bf16.h>

#define W_IN  1024
#define H_IN  1024
#define W_OUT 512
#define H_OUT 512

// Haar analysis, level 1, zero left/top pad, stride 2.
// out(h',w') depends on x rows {2h'-1, 2h'}, cols {2w'-1, 2w'} only.
__global__ void __launch_bounds__(256) dwt_haar_kernel(
    const float* __restrict__ x, float* __restrict__ out, int n_bc)
{
    const int tx = threadIdx.x;                                // 0..63 : 8 out cols each
    const int h  = blockIdx.y * blockDim.y + threadIdx.y;      // output row 0..511
    const int bc = blockIdx.z;                                 // image-channel 0..47
    const float a = 0.7071067811865476f;

    const int c0 = tx << 4;                                    // 16 input cols per thread
    const float* rowb = x + ((size_t)bc * H_IN + (size_t)(2 * h)) * W_IN;

    // t[0]/b[0] hold input col c0-1 (the left-pad carry); t[1+k] = col c0+k.
    float t[17], b[17];

    b[0] = (tx == 0) ? 0.0f : __ldg(rowb + c0 - 1);
    #pragma unroll
    for (int i = 0; i < 4; ++i) {
        float4 v = *reinterpret_cast<const float4*>(rowb + c0 + 4 * i);
        b[1 + 4 * i] = v.x; b[2 + 4 * i] = v.y;
        b[3 + 4 * i] = v.z; b[4 + 4 * i] = v.w;
    }

    if (h > 0) {
        const float* rowt = rowb - W_IN;                       // row 2h-1
        t[0] = (tx == 0) ? 0.0f : __ldg(rowt + c0 - 1);
        #pragma unroll
        for (int i = 0; i < 4; ++i) {
            float4 v = *reinterpret_cast<const float4*>(rowt + c0 + 4 * i);
            t[1 + 4 * i] = v.x; t[2 + 4 * i] = v.y;
            t[3 + 4 * i] = v.z; t[4 + 4 * i] = v.w;
        }
    } else {
        #pragma unroll
        for (int i = 0; i < 17; ++i) t[i] = 0.0f;              // top zero-pad row
    }

    float ll[8], lh[8], hl[8], hh[8];
    #pragma unroll
    for (int j = 0; j < 8; ++j) {
        // cols: 2w'-1 -> local t[2j], 2w' -> local t[2j+1]
        float t0 = t[2 * j], t1 = t[2 * j + 1];
        float b0 = b[2 * j], b1 = b[2 * j + 1];
        // horizontal pass (matches reference rounding structure)
        float h0t = a * (t0 + t1), h1t = a * (t1 - t0);
        float h0b = a * (b0 + b1), h1b = a * (b1 - b0);
        // vertical pass
        ll[j] = a * (h0t + h0b);
        lh[j] = a * (h0b - h0t);
        hl[j] = a * (h1t + h1b);
        hh[j] = a * (h1b - h1t);
    }

    const size_t P  = (size_t)n_bc * H_OUT * W_OUT;            // subband plane stride
    float* o = out + ((size_t)bc * H_OUT + h) * W_OUT + (tx << 3);

    #pragma unroll
    for (int half = 0; half < 2; ++half) {
        int j = 4 * half;
        *reinterpret_cast<float4*>(o + 0 * P + j) = make_float4(ll[j], ll[j+1], ll[j+2], ll[j+3]);
        *reinterpret_cast<float4*>(o + 1 * P + j) = make_float4(lh[j], lh[j+1], lh[j+2], lh[j+3]);
        *reinterpret_cast<float4*>(o + 2 * P + j) = make_float4(hl[j], hl[j+1], hl[j+2], hl[j+3]);
        *reinterpret_cast<float4*>(o + 3 * P + j) = make_float4(hh[j], hh[j+1], hh[j+2], hh[j+3]);
    }
}

extern "C" void kernel_launch(void* const* d_in, const int* in_sizes, int n_in,
                              void* d_out, int out_size)
{
    const float* x = (const float*)d_in[0];   // (16,3,1024,1024) fp32
    float* out = (float*)d_out;               // [LL,LH,HL,HH] each (16,3,512,512)

    const int n_bc = in_sizes[0] / (H_IN * W_IN);   // 48

    dim3 block(64, 4, 1);                     // 64 threads cover 512 out cols, 4 rows/block
    dim3 grid(1, H_OUT / 4, n_bc);
    dwt_haar_kernel<<<grid, block>>>(x, out, n_bc);
}

// round 2
// speedup vs baseline: 1.1016x; 1.1016x over previous
#include <cuda_runtime.h>
#include <cuda_bf16.h>

#define W_IN  1024
#define H_IN  1024
#define W_OUT 512
#define H_OUT 512

// Haar DWT level 1, zero left/top pad, stride 2.
// out(h',w') <- x rows {2h'-1, 2h'}, cols {2w'-1, 2w'}.
//
// Thread tid (0..255) owns input quad q=tid of one row-pair:
//   loads float4 at col 4q of rows 2h-1 and 2h (lane-contiguous LDG.128),
//   gets col 4q-1 from the neighbor lane via shfl_up (lane 0: scalar LDG),
//   emits out cols 2q, 2q+1 as float2 per subband (lane-contiguous STG.64).
__global__ void __launch_bounds__(256) dwt_haar_kernel(
    const float* __restrict__ x, float* __restrict__ out, int n_bc)
{
    const int q    = threadIdx.x;            // quad index within the row, 0..255
    const int lane = q & 31;
    const int h    = blockIdx.y;             // output row 0..511
    const int bc   = blockIdx.z;             // image*channel 0..47
    const int cb   = q << 2;                 // input col base = 4q
    const float a  = 0.7071067811865476f;

    const float* rowb = x + ((size_t)bc * H_IN + (size_t)(2 * h)) * W_IN;

    float4 vb = *reinterpret_cast<const float4*>(rowb + cb);
    float4 vt;
    float tm1s = 0.0f, bm1s = 0.0f;

    if (lane == 0 && cb != 0)
        bm1s = __ldg(rowb + cb - 1);

    if (h > 0) {
        const float* rowt = rowb - W_IN;      // input row 2h-1
        vt = *reinterpret_cast<const float4*>(rowt + cb);
        if (lane == 0 && cb != 0)
            tm1s = __ldg(rowt + cb - 1);
    } else {
        vt = make_float4(0.0f, 0.0f, 0.0f, 0.0f);   // top zero-pad
    }

    // col 4q-1 from neighbor lane's .w (left zero-pad handled by cb==0 path)
    float tm1 = __shfl_up_sync(0xffffffffu, vt.w, 1);
    float bm1 = __shfl_up_sync(0xffffffffu, vb.w, 1);
    if (lane == 0) { tm1 = tm1s; bm1 = bm1s; }

    // out col 2q   : pair (4q-1, 4q)   -> (tm1, vt.x) / (bm1, vb.x)
    // out col 2q+1 : pair (4q+1, 4q+2) -> (vt.y, vt.z) / (vb.y, vb.z)
    float h0t0 = a * (tm1 + vt.x),  h1t0 = a * (vt.x - tm1);
    float h0b0 = a * (bm1 + vb.x),  h1b0 = a * (vb.x - bm1);
    float h0t1 = a * (vt.y + vt.z), h1t1 = a * (vt.z - vt.y);
    float h0b1 = a * (vb.y + vb.z), h1b1 = a * (vb.z - vb.y);

    float ll0 = a * (h0t0 + h0b0), lh0 = a * (h0b0 - h0t0);
    float hl0 = a * (h1t0 + h1b0), hh0 = a * (h1b0 - h1t0);
    float ll1 = a * (h0t1 + h0b1), lh1 = a * (h0b1 - h0t1);
    float hl1 = a * (h1t1 + h1b1), hh1 = a * (h1b1 - h1t1);

    const size_t P = (size_t)n_bc * H_OUT * W_OUT;     // subband plane stride
    float* o = out + ((size_t)bc * H_OUT + h) * W_OUT + (q << 1);

    *reinterpret_cast<float2*>(o + 0 * P) = make_float2(ll0, ll1);
    *reinterpret_cast<float2*>(o + 1 * P) = make_float2(lh0, lh1);
    *reinterpret_cast<float2*>(o + 2 * P) = make_float2(hl0, hl1);
    *reinterpret_cast<float2*>(o + 3 * P) = make_float2(hh0, hh1);
}

extern "C" void kernel_launch(void* const* d_in, const int* in_sizes, int n_in,
                              void* d_out, int out_size)
{
    const float* x = (const float*)d_in[0];   // (16,3,1024,1024) fp32
    float* out = (float*)d_out;               // [LL,LH,HL,HH] each (16,3,512,512)

    const int n_bc = in_sizes[0] / (H_IN * W_IN);   // 48

    dim3 block(256, 1, 1);                    // 256 quads = one full output row
    dim3 grid(1, H_OUT, n_bc);
    dwt_haar_kernel<<<grid, block>>>(x, out, n_bc);
}

// round 3
// speedup vs baseline: 1.1278x; 1.0238x over previous
#include <cuda_runtime.h>
#include <cuda_bf16.h>

#define W_IN  1024
#define H_IN  1024
#define W_OUT 512
#define H_OUT 512

// Haar DWT level 1, zero left/top pad, stride 2.
// out(h',w') <- x rows {2h'-1, 2h'}, cols {2w'-1, 2w'}.
//
// Each block handles TWO output rows (h0 = 2*by, h1 = h0+1) of one (b,c) plane.
// Thread q (0..255) owns input quad q (cols 4q..4q+3) in all 4 input rows:
//   rows 2h0-1, 2h0 (pair A) and 2h0+1, 2h0+2 (pair B).
// All 4 LDG.128 are front-batched and streaming (__ldcs). Col 4q-1 comes from
// the neighbor lane's .w via shfl (lane 0: scalar load). Stores are streaming
// STG.64, lane-contiguous per subband.
__global__ void __launch_bounds__(256) dwt_haar_kernel(
    const float* __restrict__ x, float* __restrict__ out, int n_bc)
{
    const int q    = threadIdx.x;
    const int lane = q & 31;
    const int h0   = blockIdx.y << 1;        // output rows h0, h0+1
    const int bc   = blockIdx.z;
    const int cb   = q << 2;                 // input col base
    const float a  = 0.7071067811865476f;

    const float* base = x + ((size_t)bc * H_IN + (size_t)(2 * h0)) * W_IN;

    // Front-batched loads: rows 2h0-1(A-top), 2h0(A-bot), 2h0+1(B-top), 2h0+2(B-bot)
    float4 va, vb, vc, vd;
    vb = __ldcs(reinterpret_cast<const float4*>(base + cb));
    vc = __ldcs(reinterpret_cast<const float4*>(base + W_IN + cb));
    vd = __ldcs(reinterpret_cast<const float4*>(base + 2 * W_IN + cb));
    if (h0 > 0) {
        va = __ldcs(reinterpret_cast<const float4*>(base - W_IN + cb));
    } else {
        va = make_float4(0.0f, 0.0f, 0.0f, 0.0f);
    }

    // lane-0 carry scalars (col cb-1 of each row)
    float am1s = 0.0f, bm1s = 0.0f, cm1s = 0.0f, dm1s = 0.0f;
    if (lane == 0 && cb != 0) {
        bm1s = __ldg(base + cb - 1);
        cm1s = __ldg(base + W_IN + cb - 1);
        dm1s = __ldg(base + 2 * W_IN + cb - 1);
        if (h0 > 0) am1s = __ldg(base - W_IN + cb - 1);
    }

    float am1 = __shfl_up_sync(0xffffffffu, va.w, 1);
    float bm1 = __shfl_up_sync(0xffffffffu, vb.w, 1);
    float cm1 = __shfl_up_sync(0xffffffffu, vc.w, 1);
    float dm1 = __shfl_up_sync(0xffffffffu, vd.w, 1);
    if (lane == 0) { am1 = am1s; bm1 = bm1s; cm1 = cm1s; dm1 = dm1s; }

    const size_t P = (size_t)n_bc * H_OUT * W_OUT;     // subband plane stride
    float* o = out + ((size_t)bc * H_OUT + h0) * W_OUT + (q << 1);

    // ---- pair A -> output row h0 ----
    {
        float h0t0 = a * (am1 + va.x),  h1t0 = a * (va.x - am1);
        float h0b0 = a * (bm1 + vb.x),  h1b0 = a * (vb.x - bm1);
        float h0t1 = a * (va.y + va.z), h1t1 = a * (va.z - va.y);
        float h0b1 = a * (vb.y + vb.z), h1b1 = a * (vb.z - vb.y);

        __stcs(reinterpret_cast<float2*>(o + 0 * P),
               make_float2(a * (h0t0 + h0b0), a * (h0t1 + h0b1)));
        __stcs(reinterpret_cast<float2*>(o + 1 * P),
               make_float2(a * (h0b0 - h0t0), a * (h0b1 - h0t1)));
        __stcs(reinterpret_cast<float2*>(o + 2 * P),
               make_float2(a * (h1t0 + h1b0), a * (h1t1 + h1b1)));
        __stcs(reinterpret_cast<float2*>(o + 3 * P),
               make_float2(a * (h1b0 - h1t0), a * (h1b1 - h1t1)));
    }

    // ---- pair B -> output row h0+1 ----
    {
        float h0t0 = a * (cm1 + vc.x),  h1t0 = a * (vc.x - cm1);
        float h0b0 = a * (dm1 + vd.x),  h1b0 = a * (vd.x - dm1);
        float h0t1 = a * (vc.y + vc.z), h1t1 = a * (vc.z - vc.y);
        float h0b1 = a * (vd.y + vd.z), h1b1 = a * (vd.z - vd.y);

        float* o2 = o + W_OUT;
        __stcs(reinterpret_cast<float2*>(o2 + 0 * P),
               make_float2(a * (h0t0 + h0b0), a * (h0t1 + h0b1)));
        __stcs(reinterpret_cast<float2*>(o2 + 1 * P),
               make_float2(a * (h0b0 - h0t0), a * (h0b1 - h0t1)));
        __stcs(reinterpret_cast<float2*>(o2 + 2 * P),
               make_float2(a * (h1t0 + h1b0), a * (h1t1 + h1b1)));
        __stcs(reinterpret_cast<float2*>(o2 + 3 * P),
               make_float2(a * (h1b0 - h1t0), a * (h1b1 - h1t1)));
    }
}

extern "C" void kernel_launch(void* const* d_in, const int* in_sizes, int n_in,
                              void* d_out, int out_size)
{
    const float* x = (const float*)d_in[0];   // (16,3,1024,1024) fp32
    float* out = (float*)d_out;               // [LL,LH,HL,HH] each (16,3,512,512)

    const int n_bc = in_sizes[0] / (H_IN * W_IN);   // 48

    dim3 block(256, 1, 1);
    dim3 grid(1, H_OUT / 2, n_bc);            // 2 output rows per block
    dwt_haar_kernel<<<grid, block>>>(x, out, n_bc);
}